// round 16
// baseline (speedup 1.0000x reference)
#include <cuda_runtime.h>
#include <cuda_fp16.h>
#include <cstdint>

// Problem constants
constexpr int N_NODES = 50000;
constexpr int E_EDGES = 800000;
constexpr int IN_DIM  = 128;
constexpr int OUT_DIM = 128;
constexpr int R_REL   = 8;
constexpr int K_DIM   = IN_DIM * (R_REL + 1);   // 1152
constexpr int KC      = 64;                      // K per chunk (128B fp16 row)
constexpr int NCHUNK  = K_DIM / KC;              // 18
constexpr int MAXDEG  = 64;                      // Poisson(4); ample

// H / W^T storage: per (row, chunk) one 128B block = 64 fp16.
__device__ uint32_t g_cnt[R_REL * N_NODES];                      // 1.6 MB
__device__ uint32_t g_idx[(size_t)R_REL * N_NODES * MAXDEG];     // 102.4 MB
__device__ __half g_h [(size_t)N_NODES * K_DIM];                 // 115.2 MB
__device__ __half g_bt[(size_t)OUT_DIM * K_DIM];                 // 0.3 MB

// packed f32x2 helpers (family-safe: validated on this toolchain in round 1)
__device__ __forceinline__ void add_f32x2(unsigned long long& d,
                                          unsigned long long a) {
    asm("add.rn.f32x2 %0, %0, %1;" : "+l"(d) : "l"(a));
}
__device__ __forceinline__ void mul_f32x2(unsigned long long& d,
                                          unsigned long long a) {
    asm("mul.rn.f32x2 %0, %0, %1;" : "+l"(d) : "l"(a));
}
__device__ __forceinline__ unsigned long long pack2f(float lo, float hi) {
    unsigned long long r;
    asm("mov.b64 %0, {%1, %2};" : "=l"(r) : "f"(lo), "f"(hi));
    return r;
}
__device__ __forceinline__ void unpack2f(unsigned long long v,
                                         float& lo, float& hi) {
    asm("mov.b64 {%0, %1}, %2;" : "=f"(lo), "=f"(hi) : "l"(v));
}

// ---------------------------------------------------------------------------
// Kernel 1: prep = zero counters + convert W^T (merged; independent domains)
// ---------------------------------------------------------------------------
__global__ void prep_kernel(const float* __restrict__ weight,
                            const float* __restrict__ selfw) {
    const int idx = blockIdx.x * blockDim.x + threadIdx.x;
    if (idx < R_REL * N_NODES) g_cnt[idx] = 0u;
    if (idx < OUT_DIM * K_DIM) {
        const int n = idx / K_DIM;
        const int k = idx % K_DIM;
        const float v = (k < IN_DIM)
            ? selfw[(size_t)k * OUT_DIM + n]
            : weight[(size_t)(k - IN_DIM) * OUT_DIM + n];
        const int c = k / KC, p = k % KC;
        g_bt[((size_t)n * NCHUNK + c) * KC + p] = __float2half_rn(v);
    }
}

// ---------------------------------------------------------------------------
// Kernel 2: fill (bucket build) + self-row conversion, fused in one grid.
// ---------------------------------------------------------------------------
constexpr int FILL_BLOCKS = (E_EDGES + 255) / 256;           // 3125
constexpr int SELF_BLOCKS = (N_NODES + 7) / 8;               // 6250

__global__ void fill_kernel(const int* __restrict__ ei,
                            const int* __restrict__ et,
                            const float* __restrict__ x) {
    if (blockIdx.x < FILL_BLOCKS) {
        const int e = blockIdx.x * blockDim.x + threadIdx.x;
        if (e >= E_EDGES) return;
        const int src = ei[e];
        const int dst = ei[E_EDGES + e];
        const int r   = et[e];

        const int seg1 = r * N_NODES + dst;
        uint32_t p1 = atomicAdd(&g_cnt[seg1], 1u);
        if (p1 < MAXDEG) g_idx[(size_t)seg1 * MAXDEG + p1] = (uint32_t)src;

        const int seg2 = r * N_NODES + src;
        uint32_t p2 = atomicAdd(&g_cnt[seg2], 1u);
        if (p2 < MAXDEG) g_idx[(size_t)seg2 * MAXDEG + p2] = (uint32_t)dst;
    } else {
        const int v = (blockIdx.x - FILL_BLOCKS) * 8 + (threadIdx.x >> 5);
        if (v >= N_NODES) return;
        const int lane = threadIdx.x & 31;
        const float4 acc =
            reinterpret_cast<const float4*>(x)[(size_t)v * 32 + lane];
        const __half2 h01 = __floats2half2_rn(acc.x, acc.y);
        const __half2 h23 = __floats2half2_rn(acc.z, acc.w);
        const int c   = lane >> 4;                 // chunk 0 or 1
        const int off = (lane & 15) * 4;
        __half* blk = g_h + ((size_t)v * NCHUNK + c) * KC;
        *reinterpret_cast<__half2*>(blk + off)     = h01;
        *reinterpret_cast<__half2*>(blk + off + 2) = h23;
    }
}

// ---------------------------------------------------------------------------
// Kernel 3: aggregate.  One warp per (v, r) neighbor segment (r = 0..7);
// mean over relation-r neighbors -> H chunks (r+1)*2 .. (r+1)*2+1.
// Round-11 shape (32 regs, max occupancy) with packed f32x2 accumulation:
// gather loop = LDG idx + IMAD + LDG.128 + 2x ADD.f32x2 + loop  (~8 inst).
// ---------------------------------------------------------------------------
__global__ __launch_bounds__(256)
void agg_kernel(const float* __restrict__ x) {
    const int w = blockIdx.x * 8 + (threadIdx.x >> 5);
    if (w >= N_NODES * 8) return;
    const int lane = threadIdx.x & 31;
    const int v = w >> 3;
    const int r = w & 7;

    const ulonglong2* __restrict__ x2p = reinterpret_cast<const ulonglong2*>(x);

    unsigned long long a01 = 0ull, a23 = 0ull;   // packed {f0,f1},{f2,f3}

    const int seg = r * N_NODES + v;
    const uint32_t cnt = g_cnt[seg];
    const int d = (cnt < MAXDEG) ? (int)cnt : MAXDEG;
    const uint32_t* __restrict__ lst = g_idx + (size_t)seg * MAXDEG;
    for (int j = 0; j < d; j++) {
        const ulonglong2 t = x2p[(size_t)lst[j] * 32 + lane];
        add_f32x2(a01, t.x);
        add_f32x2(a23, t.y);
    }
    const float sc = (cnt > 0u) ? (1.0f / (float)cnt) : 0.0f;
    const unsigned long long scp = pack2f(sc, sc);
    mul_f32x2(a01, scp);
    mul_f32x2(a23, scp);

    float f0, f1, f2, f3;
    unpack2f(a01, f0, f1);
    unpack2f(a23, f2, f3);
    const __half2 h01 = __floats2half2_rn(f0, f1);
    const __half2 h23 = __floats2half2_rn(f2, f3);

    const int c   = (r + 1) * 2 + (lane >> 4);   // chunk index 2..17
    const int off = (lane & 15) * 4;             // fp16 position within chunk
    __half* blk = g_h + ((size_t)v * NCHUNK + c) * KC;
    *reinterpret_cast<__half2*>(blk + off)     = h01;
    *reinterpret_cast<__half2*>(blk + off + 2) = h23;
}

// ---------------------------------------------------------------------------
// mma.sync / cp.async helpers
// ---------------------------------------------------------------------------
__device__ __forceinline__ uint32_t smem_u32(const void* p) {
    uint32_t a;
    asm("{ .reg .u64 t; cvta.to.shared.u64 t, %1; cvt.u32.u64 %0, t; }"
        : "=r"(a) : "l"(p));
    return a;
}
__device__ __forceinline__ uint64_t gmem_u64(const void* p) {
    uint64_t a;
    asm("cvta.to.global.u64 %0, %1;" : "=l"(a) : "l"(p));
    return a;
}
__device__ __forceinline__ uint32_t sw128(uint32_t o) {
    return o ^ ((o >> 3) & 0x70);
}
__device__ __forceinline__ void cp16(uint32_t dst, uint64_t src) {
    asm volatile("cp.async.cg.shared.global [%0], [%1], 16;"
                 :: "r"(dst), "l"(src) : "memory");
}
__device__ __forceinline__ void cp_commit() {
    asm volatile("cp.async.commit_group;" ::: "memory");
}
template<int n> __device__ __forceinline__ void cp_wait() {
    asm volatile("cp.async.wait_group %0;" :: "n"(n) : "memory");
}
__device__ __forceinline__ void ldsm_x4(uint32_t addr,
                                        uint32_t& r0, uint32_t& r1,
                                        uint32_t& r2, uint32_t& r3) {
    asm volatile("ldmatrix.sync.aligned.m8n8.x4.shared.b16 {%0,%1,%2,%3}, [%4];"
                 : "=r"(r0), "=r"(r1), "=r"(r2), "=r"(r3) : "r"(addr));
}
__device__ __forceinline__ void mma16816(float* c, const uint32_t* a,
                                         uint32_t b0, uint32_t b1) {
    asm volatile(
        "mma.sync.aligned.m16n8k16.row.col.f32.f16.f16.f32 "
        "{%0,%1,%2,%3}, {%4,%5,%6,%7}, {%8,%9}, {%0,%1,%2,%3};"
        : "+f"(c[0]), "+f"(c[1]), "+f"(c[2]), "+f"(c[3])
        : "r"(a[0]), "r"(a[1]), "r"(a[2]), "r"(a[3]), "r"(b0), "r"(b1));
}

// Smem: 3 stages x {A tile 16KB, B tile 16KB}. Tile row = 128B (64 fp16).
constexpr int STAGE   = 32768;
constexpr int OFF_B   = 16384;
constexpr int SMEM_TOTAL = 3 * STAGE;   // 96 KB -> 2 CTAs/SM

// ---------------------------------------------------------------------------
// Kernel 4: out = H @ Wcat, pure fp16 GEMM (round-11 form, local optimum).
// CTA 128x128, 8 warps (4x2), KC=64, 3-stage cp.async ring, ONE sync/iter.
// ---------------------------------------------------------------------------
__global__ __launch_bounds__(256, 2)
void gemm_kernel(float* __restrict__ out) {
    extern __shared__ char smem[];
    const uint32_t sb = smem_u32(smem);
    const int tid  = threadIdx.x;
    const int wid  = tid >> 5;
    const int lane = tid & 31;
    const int m0   = blockIdx.x * 128;

    const int wm = wid & 3, wn = wid >> 2;
    const int mbase = wm * 32, nbase = wn * 64;
    const int rlane = lane & 15;
    const int klane = (lane >> 4) * 16;

    // cp.async mapping: 2 threads/row, each one 64B half (4x cp16)
    const int crow = tid >> 1;
    const int chalf = (tid & 1) * 64;
    const int arow = (m0 + crow < N_NODES) ? (m0 + crow) : (N_NODES - 1);
    const uint64_t gA = gmem_u64(g_h)  + ((size_t)arow * NCHUNK) * 128 + chalf;
    const uint64_t gB = gmem_u64(g_bt) + ((size_t)crow * NCHUNK) * 128 + chalf;
    const uint32_t rowbase = (uint32_t)(crow * 128 + chalf);

    auto issue = [&](int ch, int s) {
        const uint32_t da = sb + s * STAGE;
        const uint32_t db = da + OFF_B;
        const uint64_t sa = gA + (size_t)ch * 128;
        const uint64_t sbsrc = gB + (size_t)ch * 128;
        // swizzle applied PER 16-byte transfer (matches ldmatrix side)
        #pragma unroll
        for (int i = 0; i < 4; i++) cp16(da + sw128(rowbase + i * 16), sa + i * 16);
        #pragma unroll
        for (int i = 0; i < 4; i++) cp16(db + sw128(rowbase + i * 16), sbsrc + i * 16);
        cp_commit();
    };

    float acc[2][8][4];
    #pragma unroll
    for (int i = 0; i < 2; i++)
        #pragma unroll
        for (int j = 0; j < 8; j++)
            #pragma unroll
            for (int q = 0; q < 4; q++) acc[i][j][q] = 0.f;

    issue(0, 0);
    issue(1, 1);

    for (int ch = 0; ch < NCHUNK; ch++) {
        // One barrier per iter: makes stage-ch data visible AND proves all
        // warps are done reading the stage issue(ch+2) will overwrite.
        if (ch + 1 < NCHUNK) cp_wait<1>(); else cp_wait<0>();
        __syncthreads();
        if (ch + 2 < NCHUNK) issue(ch + 2, (ch + 2) % 3);

        const uint32_t sA = sb + (ch % 3) * STAGE;
        const uint32_t sB = sA + OFF_B;
        #pragma unroll
        for (int kk = 0; kk < 4; kk++) {
            const uint32_t kb = (uint32_t)(kk * 32 + klane);
            uint32_t a[2][4];
            #pragma unroll
            for (int g = 0; g < 2; g++) {
                const uint32_t ro = (uint32_t)((mbase + g * 16 + rlane) * 128);
                ldsm_x4(sA + sw128(ro + kb), a[g][0], a[g][1], a[g][2], a[g][3]);
            }
            uint32_t b[4][4];
            #pragma unroll
            for (int nt = 0; nt < 4; nt++) {
                const uint32_t ro = (uint32_t)((nbase + nt * 16 + rlane) * 128);
                ldsm_x4(sB + sw128(ro + kb), b[nt][0], b[nt][1], b[nt][2], b[nt][3]);
            }
            // 16 MMAs, all distinct accumulators
            #pragma unroll
            for (int g = 0; g < 2; g++)
                #pragma unroll
                for (int nt = 0; nt < 4; nt++) {
                    mma16816(acc[g][nt * 2 + 0], a[g], b[nt][0], b[nt][2]);
                    mma16816(acc[g][nt * 2 + 1], a[g], b[nt][1], b[nt][3]);
                }
        }
    }

    // ---- epilogue ----
    const int gq = lane >> 2;
    const int tq = lane & 3;
    #pragma unroll
    for (int g = 0; g < 2; g++) {
        const int row_lo = m0 + mbase + g * 16 + gq;
        const int row_hi = row_lo + 8;
        #pragma unroll
        for (int nt = 0; nt < 8; nt++) {
            const int col = nbase + nt * 8 + tq * 2;
            if (row_lo < N_NODES)
                *reinterpret_cast<float2*>(out + (size_t)row_lo * OUT_DIM + col) =
                    make_float2(acc[g][nt][0], acc[g][nt][1]);
            if (row_hi < N_NODES)
                *reinterpret_cast<float2*>(out + (size_t)row_hi * OUT_DIM + col) =
                    make_float2(acc[g][nt][2], acc[g][nt][3]);
        }
    }
}

// ---------------------------------------------------------------------------
// Launch
// ---------------------------------------------------------------------------
extern "C" void kernel_launch(void* const* d_in, const int* in_sizes, int n_in,
                              void* d_out, int out_size) {
    const float* x      = (const float*)d_in[0];
    const float* weight = (const float*)d_in[1];
    const float* selfw  = (const float*)d_in[2];
    const int*   ei     = (const int*)d_in[3];
    const int*   et     = (const int*)d_in[4];
    float*       out    = (float*)d_out;

    cudaFuncSetAttribute(gemm_kernel,
                         cudaFuncAttributeMaxDynamicSharedMemorySize, SMEM_TOTAL);

    prep_kernel<<<(R_REL * N_NODES + 255) / 256, 256>>>(weight, selfw);
    fill_kernel<<<FILL_BLOCKS + SELF_BLOCKS, 256>>>(ei, et, x);

    const int segs = N_NODES * 8;                       // 400000 warps
    agg_kernel<<<(segs + 7) / 8, 256>>>(x);

    gemm_kernel<<<(N_NODES + 127) / 128, 256, SMEM_TOTAL>>>(out);
}

// round 17
// speedup vs baseline: 1.0388x; 1.0388x over previous
#include <cuda_runtime.h>
#include <cuda_fp16.h>
#include <cstdint>

// Problem constants
constexpr int N_NODES = 50000;
constexpr int E_EDGES = 800000;
constexpr int IN_DIM  = 128;
constexpr int OUT_DIM = 128;
constexpr int R_REL   = 8;
constexpr int K_DIM   = IN_DIM * (R_REL + 1);   // 1152
constexpr int KC      = 64;                      // K per chunk (128B fp16 row)
constexpr int NCHUNK  = K_DIM / KC;              // 18
constexpr int MAXDEG  = 64;                      // Poisson(4); ample

// H / W^T storage: per (row, chunk) one 128B block = 64 fp16.
__device__ uint32_t g_cnt[R_REL * N_NODES];                      // 1.6 MB
__device__ uint32_t g_idx[(size_t)R_REL * N_NODES * MAXDEG];     // 102.4 MB
__device__ __half g_h [(size_t)N_NODES * K_DIM];                 // 115.2 MB
__device__ __half g_bt[(size_t)OUT_DIM * K_DIM];                 // 0.3 MB

// ---------------------------------------------------------------------------
// Kernel 1: prep = zero counters + convert W^T (merged; independent domains)
// ---------------------------------------------------------------------------
__global__ void prep_kernel(const float* __restrict__ weight,
                            const float* __restrict__ selfw) {
    const int idx = blockIdx.x * blockDim.x + threadIdx.x;
    if (idx < R_REL * N_NODES) g_cnt[idx] = 0u;
    if (idx < OUT_DIM * K_DIM) {
        const int n = idx / K_DIM;
        const int k = idx % K_DIM;
        const float v = (k < IN_DIM)
            ? selfw[(size_t)k * OUT_DIM + n]
            : weight[(size_t)(k - IN_DIM) * OUT_DIM + n];
        const int c = k / KC, p = k % KC;
        g_bt[((size_t)n * NCHUNK + c) * KC + p] = __float2half_rn(v);
    }
}

// ---------------------------------------------------------------------------
// Kernel 2: fill (bucket build) + self-row conversion, fused in one grid.
// ---------------------------------------------------------------------------
constexpr int FILL_BLOCKS = (E_EDGES + 255) / 256;           // 3125
constexpr int SELF_BLOCKS = (N_NODES + 7) / 8;               // 6250

__global__ void fill_kernel(const int* __restrict__ ei,
                            const int* __restrict__ et,
                            const float* __restrict__ x) {
    if (blockIdx.x < FILL_BLOCKS) {
        const int e = blockIdx.x * blockDim.x + threadIdx.x;
        if (e >= E_EDGES) return;
        const int src = ei[e];
        const int dst = ei[E_EDGES + e];
        const int r   = et[e];

        const int seg1 = r * N_NODES + dst;
        uint32_t p1 = atomicAdd(&g_cnt[seg1], 1u);
        if (p1 < MAXDEG) g_idx[(size_t)seg1 * MAXDEG + p1] = (uint32_t)src;

        const int seg2 = r * N_NODES + src;
        uint32_t p2 = atomicAdd(&g_cnt[seg2], 1u);
        if (p2 < MAXDEG) g_idx[(size_t)seg2 * MAXDEG + p2] = (uint32_t)dst;
    } else {
        const int v = (blockIdx.x - FILL_BLOCKS) * 8 + (threadIdx.x >> 5);
        if (v >= N_NODES) return;
        const int lane = threadIdx.x & 31;
        const float4 acc =
            reinterpret_cast<const float4*>(x)[(size_t)v * 32 + lane];
        const __half2 h01 = __floats2half2_rn(acc.x, acc.y);
        const __half2 h23 = __floats2half2_rn(acc.z, acc.w);
        const int c   = lane >> 4;                 // chunk 0 or 1
        const int off = (lane & 15) * 4;
        __half* blk = g_h + ((size_t)v * NCHUNK + c) * KC;
        *reinterpret_cast<__half2*>(blk + off)     = h01;
        *reinterpret_cast<__half2*>(blk + off + 2) = h23;
    }
}

// ---------------------------------------------------------------------------
// Kernel 3: aggregate.  One warp per (v, r) neighbor segment (r = 0..7);
// mean over relation-r neighbors -> H chunks (r+1)*2 .. (r+1)*2+1.
// FROZEN round-15 form: simple float4 loop, 32 regs, max occupancy.
// (4 variants tried — registers, extra warps, shuffles, f32x2 — all slower.)
// ---------------------------------------------------------------------------
__global__ __launch_bounds__(256)
void agg_kernel(const float* __restrict__ x) {
    const int w = blockIdx.x * 8 + (threadIdx.x >> 5);
    if (w >= N_NODES * 8) return;
    const int lane = threadIdx.x & 31;
    const int v = w >> 3;
    const int r = w & 7;

    const float4* __restrict__ x4 = reinterpret_cast<const float4*>(x);
    float4 acc = make_float4(0.f, 0.f, 0.f, 0.f);

    const int seg = r * N_NODES + v;
    const uint32_t cnt = g_cnt[seg];
    const int d = (cnt < MAXDEG) ? (int)cnt : MAXDEG;
    const uint32_t* __restrict__ lst = g_idx + (size_t)seg * MAXDEG;
    for (int j = 0; j < d; j++) {
        const float4 t = x4[(size_t)lst[j] * 32 + lane];
        acc.x += t.x; acc.y += t.y; acc.z += t.z; acc.w += t.w;
    }
    const float sc = (cnt > 0u) ? (1.0f / (float)cnt) : 0.0f;

    const __half2 h01 = __floats2half2_rn(acc.x * sc, acc.y * sc);
    const __half2 h23 = __floats2half2_rn(acc.z * sc, acc.w * sc);

    const int c   = (r + 1) * 2 + (lane >> 4);   // chunk index 2..17
    const int off = (lane & 15) * 4;             // fp16 position within chunk
    __half* blk = g_h + ((size_t)v * NCHUNK + c) * KC;
    *reinterpret_cast<__half2*>(blk + off)     = h01;
    *reinterpret_cast<__half2*>(blk + off + 2) = h23;
}

// ---------------------------------------------------------------------------
// mma.sync / cp.async helpers
// ---------------------------------------------------------------------------
__device__ __forceinline__ uint32_t smem_u32(const void* p) {
    uint32_t a;
    asm("{ .reg .u64 t; cvta.to.shared.u64 t, %1; cvt.u32.u64 %0, t; }"
        : "=r"(a) : "l"(p));
    return a;
}
__device__ __forceinline__ uint64_t gmem_u64(const void* p) {
    uint64_t a;
    asm("cvta.to.global.u64 %0, %1;" : "=l"(a) : "l"(p));
    return a;
}
__device__ __forceinline__ uint32_t sw128(uint32_t o) {
    return o ^ ((o >> 3) & 0x70);
}
__device__ __forceinline__ void cp16(uint32_t dst, uint64_t src) {
    asm volatile("cp.async.cg.shared.global [%0], [%1], 16;"
                 :: "r"(dst), "l"(src) : "memory");
}
__device__ __forceinline__ void cp_commit() {
    asm volatile("cp.async.commit_group;" ::: "memory");
}
template<int n> __device__ __forceinline__ void cp_wait() {
    asm volatile("cp.async.wait_group %0;" :: "n"(n) : "memory");
}
__device__ __forceinline__ void ldsm_x4(uint32_t addr,
                                        uint32_t& r0, uint32_t& r1,
                                        uint32_t& r2, uint32_t& r3) {
    asm volatile("ldmatrix.sync.aligned.m8n8.x4.shared.b16 {%0,%1,%2,%3}, [%4];"
                 : "=r"(r0), "=r"(r1), "=r"(r2), "=r"(r3) : "r"(addr));
}
__device__ __forceinline__ void mma16816(float* c, const uint32_t* a,
                                         uint32_t b0, uint32_t b1) {
    asm volatile(
        "mma.sync.aligned.m16n8k16.row.col.f32.f16.f16.f32 "
        "{%0,%1,%2,%3}, {%4,%5,%6,%7}, {%8,%9}, {%0,%1,%2,%3};"
        : "+f"(c[0]), "+f"(c[1]), "+f"(c[2]), "+f"(c[3])
        : "r"(a[0]), "r"(a[1]), "r"(a[2]), "r"(a[3]), "r"(b0), "r"(b1));
}

// Smem: 3 stages x {A tile 16KB, B tile 16KB}. Tile row = 128B (64 fp16).
constexpr int STAGE   = 32768;
constexpr int OFF_B   = 16384;
constexpr int SMEM_TOTAL = 3 * STAGE;   // 96 KB -> 2 CTAs/SM

// ---------------------------------------------------------------------------
// Kernel 4: out = H @ Wcat, pure fp16 GEMM (round-11 form, local optimum).
// CTA 128x128, 8 warps (4x2), KC=64, 3-stage cp.async ring, ONE sync/iter.
// Tile order REVERSED: wave 1 reads the most-recently-written (still
// L2-resident) tail of H; DRAM misses deferred to wave 2.
// ---------------------------------------------------------------------------
__global__ __launch_bounds__(256, 2)
void gemm_kernel(float* __restrict__ out) {
    extern __shared__ char smem[];
    const uint32_t sb = smem_u32(smem);
    const int tid  = threadIdx.x;
    const int wid  = tid >> 5;
    const int lane = tid & 31;
    const int m0   = (int)(gridDim.x - 1 - blockIdx.x) * 128;   // reversed

    const int wm = wid & 3, wn = wid >> 2;
    const int mbase = wm * 32, nbase = wn * 64;
    const int rlane = lane & 15;
    const int klane = (lane >> 4) * 16;

    // cp.async mapping: 2 threads/row, each one 64B half (4x cp16)
    const int crow = tid >> 1;
    const int chalf = (tid & 1) * 64;
    const int arow = (m0 + crow < N_NODES) ? (m0 + crow) : (N_NODES - 1);
    const uint64_t gA = gmem_u64(g_h)  + ((size_t)arow * NCHUNK) * 128 + chalf;
    const uint64_t gB = gmem_u64(g_bt) + ((size_t)crow * NCHUNK) * 128 + chalf;
    const uint32_t rowbase = (uint32_t)(crow * 128 + chalf);

    auto issue = [&](int ch, int s) {
        const uint32_t da = sb + s * STAGE;
        const uint32_t db = da + OFF_B;
        const uint64_t sa = gA + (size_t)ch * 128;
        const uint64_t sbsrc = gB + (size_t)ch * 128;
        // swizzle applied PER 16-byte transfer (matches ldmatrix side)
        #pragma unroll
        for (int i = 0; i < 4; i++) cp16(da + sw128(rowbase + i * 16), sa + i * 16);
        #pragma unroll
        for (int i = 0; i < 4; i++) cp16(db + sw128(rowbase + i * 16), sbsrc + i * 16);
        cp_commit();
    };

    float acc[2][8][4];
    #pragma unroll
    for (int i = 0; i < 2; i++)
        #pragma unroll
        for (int j = 0; j < 8; j++)
            #pragma unroll
            for (int q = 0; q < 4; q++) acc[i][j][q] = 0.f;

    issue(0, 0);
    issue(1, 1);

    for (int ch = 0; ch < NCHUNK; ch++) {
        // One barrier per iter: makes stage-ch data visible AND proves all
        // warps are done reading the stage issue(ch+2) will overwrite.
        if (ch + 1 < NCHUNK) cp_wait<1>(); else cp_wait<0>();
        __syncthreads();
        if (ch + 2 < NCHUNK) issue(ch + 2, (ch + 2) % 3);

        const uint32_t sA = sb + (ch % 3) * STAGE;
        const uint32_t sB = sA + OFF_B;
        #pragma unroll
        for (int kk = 0; kk < 4; kk++) {
            const uint32_t kb = (uint32_t)(kk * 32 + klane);
            uint32_t a[2][4];
            #pragma unroll
            for (int g = 0; g < 2; g++) {
                const uint32_t ro = (uint32_t)((mbase + g * 16 + rlane) * 128);
                ldsm_x4(sA + sw128(ro + kb), a[g][0], a[g][1], a[g][2], a[g][3]);
            }
            uint32_t b[4][4];
            #pragma unroll
            for (int nt = 0; nt < 4; nt++) {
                const uint32_t ro = (uint32_t)((nbase + nt * 16 + rlane) * 128);
                ldsm_x4(sB + sw128(ro + kb), b[nt][0], b[nt][1], b[nt][2], b[nt][3]);
            }
            // 16 MMAs, all distinct accumulators
            #pragma unroll
            for (int g = 0; g < 2; g++)
                #pragma unroll
                for (int nt = 0; nt < 4; nt++) {
                    mma16816(acc[g][nt * 2 + 0], a[g], b[nt][0], b[nt][2]);
                    mma16816(acc[g][nt * 2 + 1], a[g], b[nt][1], b[nt][3]);
                }
        }
    }

    // ---- epilogue ----
    const int gq = lane >> 2;
    const int tq = lane & 3;
    #pragma unroll
    for (int g = 0; g < 2; g++) {
        const int row_lo = m0 + mbase + g * 16 + gq;
        const int row_hi = row_lo + 8;
        #pragma unroll
        for (int nt = 0; nt < 8; nt++) {
            const int col = nbase + nt * 8 + tq * 2;
            if (row_lo < N_NODES)
                *reinterpret_cast<float2*>(out + (size_t)row_lo * OUT_DIM + col) =
                    make_float2(acc[g][nt][0], acc[g][nt][1]);
            if (row_hi < N_NODES)
                *reinterpret_cast<float2*>(out + (size_t)row_hi * OUT_DIM + col) =
                    make_float2(acc[g][nt][2], acc[g][nt][3]);
        }
    }
}

// ---------------------------------------------------------------------------
// Launch
// ---------------------------------------------------------------------------
extern "C" void kernel_launch(void* const* d_in, const int* in_sizes, int n_in,
                              void* d_out, int out_size) {
    const float* x      = (const float*)d_in[0];
    const float* weight = (const float*)d_in[1];
    const float* selfw  = (const float*)d_in[2];
    const int*   ei     = (const int*)d_in[3];
    const int*   et     = (const int*)d_in[4];
    float*       out    = (float*)d_out;

    cudaFuncSetAttribute(gemm_kernel,
                         cudaFuncAttributeMaxDynamicSharedMemorySize, SMEM_TOTAL);

    prep_kernel<<<(R_REL * N_NODES + 255) / 256, 256>>>(weight, selfw);
    fill_kernel<<<FILL_BLOCKS + SELF_BLOCKS, 256>>>(ei, et, x);

    const int segs = N_NODES * 8;                       // 400000 warps
    agg_kernel<<<(segs + 7) / 8, 256>>>(x);

    gemm_kernel<<<(N_NODES + 127) / 128, 256, SMEM_TOTAL>>>(out);
}